// round 12
// baseline (speedup 1.0000x reference)
#include <cuda_runtime.h>
#include <cuda_fp16.h>
#include <cstdint>

#define NTOK 32768
#define HDIM 768
#define NEXP 8
#define NPAIR 28
#define TM 128
#define MAXT2 (NTOK / TM + NPAIR)    // 284

// GEMM tiles (proven mainloop config)
#define CTM 128
#define CTK 32
#define KT  (HDIM / CTK)              // 24 stages
#define NSTG 4
#define ROWB 80
#define TILEB (128 * ROWB)            // 10240
#define STAGEB (2 * TILEB)
#define SMEM_BYTES (NSTG * STAGEB)    // 81920 -> 2 CTAs/SM

#define RBLK (NTOK / 8)               // 4096 router blocks
#define WBLK (NEXP * HDIM * HDIM / 1024)  // 4608 convert blocks

typedef unsigned long long u64;

// ---------------- scratch ----------------
__device__ int   g_cnt [NPAIR];       // zero at load; last prep block re-zeros per replay
__device__ int   g_mend[NPAIR];
__device__ int   g_ts  [NPAIR + 1];
__device__ int   g_done;
__device__ int   g_tok [NPAIR][NTOK];
__device__ float g_pwa [NPAIR][NTOK];
__device__ float g_pwb [NPAIR][NTOK];

__device__ __half g_xh[NTOK * HDIM];
__device__ __half g_wh[NEXP * HDIM * HDIM];

// ---------------- helpers ----------------
__device__ __forceinline__ void cpa16(uint32_t s, const void* g) {
    asm volatile("cp.async.cg.shared.global [%0], [%1], 16;" :: "r"(s), "l"(g));
}
__device__ __forceinline__ void cp_commit() { asm volatile("cp.async.commit_group;"); }
template <int N> __device__ __forceinline__ void cp_wait() {
    asm volatile("cp.async.wait_group %0;" :: "n"(N));
}
__device__ __forceinline__ void mma16816_f32(float* c, const uint32_t* a, const uint32_t* b) {
    asm volatile(
        "mma.sync.aligned.m16n8k16.row.col.f32.f16.f16.f32 "
        "{%0,%1,%2,%3}, {%4,%5,%6,%7}, {%8,%9}, {%0,%1,%2,%3};"
        : "+f"(c[0]), "+f"(c[1]), "+f"(c[2]), "+f"(c[3])
        : "r"(a[0]), "r"(a[1]), "r"(a[2]), "r"(a[3]), "r"(b[0]), "r"(b[1]));
}
__device__ __forceinline__ void ldsm4(uint32_t* r, uint32_t addr) {
    asm volatile("ldmatrix.sync.aligned.m8n8.x4.shared.b16 {%0,%1,%2,%3}, [%4];"
        : "=r"(r[0]), "=r"(r[1]), "=r"(r[2]), "=r"(r[3]) : "r"(addr));
}
__device__ __forceinline__ int pair_id(int a, int b) {   // a < b
    return a * (2 * NEXP - 1 - a) / 2 + (b - a - 1);
}

// ---------------- kernel 1: fused prep — router + weight convert + inline scan ----------------
__global__ __launch_bounds__(256) void prep_kernel(
    const float* __restrict__ x, const float* __restrict__ rw,
    const float* __restrict__ rb, const float* __restrict__ w)
{
    if (blockIdx.x >= RBLK) {
        // ---- weight convert path ----
        int i = (blockIdx.x - RBLK) * 256 + threadIdx.x;   // one float4 per thread
        float4 v = ((const float4*)w)[i];
        ((__half2*)g_wh)[2 * i]     = __floats2half2_rn(v.x, v.y);
        ((__half2*)g_wh)[2 * i + 1] = __floats2half2_rn(v.z, v.w);
    } else {
        // ---- router path (fused x hi conversion + direct bucket write) ----
        __shared__ float s_rw[NEXP * HDIM];
        for (int i = threadIdx.x; i < NEXP * HDIM; i += 256) s_rw[i] = rw[i];
        __syncthreads();

        int warp = threadIdx.x >> 5, lane = threadIdx.x & 31;
        int tok = (blockIdx.x << 3) + warp;
        const float4* xr = (const float4*)(x + (size_t)tok * HDIM);
        __half2* xh = (__half2*)(g_xh + (size_t)tok * HDIM);

        float acc[NEXP];
#pragma unroll
        for (int e = 0; e < NEXP; e++) acc[e] = 0.f;
#pragma unroll
        for (int i = 0; i < HDIM / 128; i++) {
            int idx = i * 32 + lane;
            float4 v = xr[idx];
            xh[2 * idx]     = __floats2half2_rn(v.x, v.y);
            xh[2 * idx + 1] = __floats2half2_rn(v.z, v.w);
#pragma unroll
            for (int e = 0; e < NEXP; e++) {
                float4 w4 = ((const float4*)(s_rw + e * HDIM))[idx];
                acc[e] = fmaf(v.x, w4.x, fmaf(v.y, w4.y, fmaf(v.z, w4.z, fmaf(v.w, w4.w, acc[e]))));
            }
        }
#pragma unroll
        for (int e = 0; e < NEXP; e++)
#pragma unroll
            for (int o = 16; o > 0; o >>= 1)
                acc[e] += __shfl_xor_sync(0xffffffffu, acc[e], o);

        if (lane == 0) {
            float s[NEXP];
#pragma unroll
            for (int e = 0; e < NEXP; e++) s[e] = acc[e] + rb[e];
            float m = s[0];
#pragma unroll
            for (int e = 1; e < NEXP; e++) m = fmaxf(m, s[e]);
            float p[NEXP]; float Z = 0.f;
#pragma unroll
            for (int e = 0; e < NEXP; e++) { p[e] = expf(s[e] - m); Z += p[e]; }
            int e0 = 0;
#pragma unroll
            for (int e = 1; e < NEXP; e++) if (p[e] > p[e0]) e0 = e;
            int e1 = (e0 == 0) ? 1 : 0;
#pragma unroll
            for (int e = 0; e < NEXP; e++) if (e != e0 && p[e] > p[e1]) e1 = e;
            float p0 = p[e0] / Z, p1 = p[e1] / Z;
            float inv = 1.f / (p0 + p1 + 1e-9f);
            int a = min(e0, e1), b = max(e0, e1);
            float wa = (e0 < e1) ? p0 * inv : p1 * inv;
            float wb = (e0 < e1) ? p1 * inv : p0 * inv;
            int pid = pair_id(a, b);
            int pos = atomicAdd(&g_cnt[pid], 1);
            g_tok[pid][pos] = tok;
            g_pwa[pid][pos] = wa;
            g_pwb[pid][pos] = wb;
        }
    }

    // ---- last-block-done: inline scan (replaces scan_kernel) ----
    __syncthreads();
    __threadfence();
    if (threadIdx.x == 0) {
        int ticket = atomicAdd(&g_done, 1);
        if (ticket == (int)gridDim.x - 1) {
            g_done = 0;                      // reset for next graph replay
            int t = 0;
            for (int p = 0; p < NPAIR; p++) {
                g_ts[p] = t;
                int c = g_cnt[p];
                g_mend[p] = c;
                g_cnt[p] = 0;                // reset for next graph replay
                t += (c + TM - 1) >> 7;
            }
            g_ts[NPAIR] = t;
            __threadfence();
        }
    }
}

// ---------------- kernel 2: pair GEMM — N-tile on x (full), pair-tile on y ----------------
__global__ __launch_bounds__(256, 2)
void moe_pair(const float* __restrict__ eb, float* __restrict__ out)
{
    extern __shared__ __align__(128) char smem[];
    const uint32_t sb = (uint32_t)__cvta_generic_to_shared(smem);

    __shared__ int   sMeta[3];
    __shared__ int   sTok[CTM];
    __shared__ float sWa[CTM];
    __shared__ float sWb[CTM];
    __shared__ float sBias[128];

    int tid = threadIdx.x;
    int wid = tid >> 5, lane = tid & 31;

    if (tid == 0) {
        int bx = blockIdx.y;                 // pair-tile index (swapped to y)
        if (bx >= g_ts[NPAIR]) sMeta[0] = -1;
        else {
            int p = 0;
            while (g_ts[p + 1] <= bx) p++;
            sMeta[0] = p;
            sMeta[1] = (bx - g_ts[p]) << 7;
            sMeta[2] = g_mend[p];
        }
    }
    __syncthreads();
    int p = sMeta[0];
    if (p < 0) return;
    int m0 = sMeta[1], mEnd = sMeta[2];
    // decode pair -> (ea, eb_)
    int ea = 0, rem = p, span = NEXP - 1;
    while (rem >= span) { rem -= span; ea++; span--; }
    int eb_ = ea + 1 + rem;
    int nBase = blockIdx.x << 6;             // N-tile (swapped to x) * 64

    if (tid < CTM) {
        int pp = m0 + tid;
        int pc = pp < mEnd ? pp : mEnd - 1;
        sTok[tid] = g_tok[p][pc];
        sWa[tid]  = g_pwa[p][pc];
        sWb[tid]  = g_pwb[p][pc];
    }
    if (tid < 128) {
        int ex = (tid < 64) ? ea : eb_;
        sBias[tid] = __ldg(eb + ex * HDIM + nBase + (tid & 63));
    }
    __syncthreads();

    // ---- stage loader ----
    int lrow = tid >> 1;
    int lc0  = (tid & 1) * 2;
    size_t gAr = (size_t)sTok[lrow] * HDIM;
    int bexp = (lrow < 64) ? ea : eb_;
    size_t gBr = ((size_t)bexp * HDIM + nBase + (lrow & 63)) * HDIM;

    auto load_stage = [&](int kt, int buf) {
        uint32_t sbase = sb + (uint32_t)buf * STAGEB;
        int kc = kt * CTK;
#pragma unroll
        for (int t = 0; t < 2; t++) {
            int c = lc0 + t;
            uint32_t so = (uint32_t)(lrow * ROWB + c * 16);
            cpa16(sbase + 0 * TILEB + so, g_xh + gAr + kc + c * 8);
            cpa16(sbase + 1 * TILEB + so, g_wh + gBr + kc + c * 8);
        }
    };

    load_stage(0, 0); cp_commit();
    load_stage(1, 1); cp_commit();
    load_stage(2, 2); cp_commit();

    int warp_m = wid >> 1, warp_n = wid & 1;
    int r = lane >> 2, q = lane & 3;

    uint32_t aOff = (uint32_t)((warp_m * 32 + (lane & 15)) * ROWB + ((lane >> 4) << 4));
    uint32_t bLane = (uint32_t)((((lane >> 4) << 3) + (lane & 7)) * ROWB
                                + (((lane >> 3) & 1) << 4));

    float acc[2][2][4][4];
#pragma unroll
    for (int x = 0; x < 2; x++)
#pragma unroll
        for (int mt = 0; mt < 2; mt++)
#pragma unroll
            for (int nt = 0; nt < 4; nt++)
#pragma unroll
                for (int i = 0; i < 4; i++) acc[x][mt][nt][i] = 0.f;

    for (int kt = 0; kt < KT; kt++) {
        int buf = kt & 3;
        if (kt <= KT - 3) cp_wait<2>();
        else if (kt == KT - 2) cp_wait<1>();
        else cp_wait<0>();
        __syncthreads();
        if (kt + 3 < KT) { load_stage(kt + 3, (kt + 3) & 3); cp_commit(); }

        uint32_t tb = sb + (uint32_t)buf * STAGEB;

#pragma unroll
        for (int k16 = 0; k16 < 2; k16++) {
            uint32_t kb = (uint32_t)(k16 * 32);
            uint32_t ah[2][4], bf[2][4][2];
#pragma unroll
            for (int mt = 0; mt < 2; mt++)
                ldsm4(ah[mt], tb + aOff + (uint32_t)(mt * 16 * ROWB) + kb);
#pragma unroll
            for (int x = 0; x < 2; x++)
#pragma unroll
                for (int ntp = 0; ntp < 2; ntp++) {
                    uint32_t regs[4];
                    uint32_t grpRow = (uint32_t)((x * 64 + warp_n * 32 + ntp * 16) * ROWB);
                    ldsm4(regs, tb + TILEB + bLane + grpRow + kb);
                    bf[x][2 * ntp][0] = regs[0]; bf[x][2 * ntp][1] = regs[1];
                    bf[x][2 * ntp + 1][0] = regs[2]; bf[x][2 * ntp + 1][1] = regs[3];
                }
#pragma unroll
            for (int x = 0; x < 2; x++)
#pragma unroll
                for (int mt = 0; mt < 2; mt++)
#pragma unroll
                    for (int nt = 0; nt < 4; nt++)
                        mma16816_f32(acc[x][mt][nt], ah[mt], bf[x][nt]);
        }
    }

    // ---- epilogue: out = wa*(ya+ba) + wb*(yb+bb) ----
#pragma unroll
    for (int mt = 0; mt < 2; mt++) {
        int lr0 = warp_m * 32 + mt * 16 + r;
        int lr1 = lr0 + 8;
        bool v0 = (m0 + lr0) < mEnd;
        bool v1 = (m0 + lr1) < mEnd;
        float wa0 = sWa[lr0], wb0 = sWb[lr0];
        float wa1 = sWa[lr1], wb1 = sWb[lr1];
        float* o0 = out + (size_t)sTok[lr0] * HDIM + nBase;
        float* o1 = out + (size_t)sTok[lr1] * HDIM + nBase;
#pragma unroll
        for (int nt = 0; nt < 4; nt++) {
            int lc = warp_n * 32 + nt * 8 + 2 * q;
            float bax = sBias[lc], bay = sBias[lc + 1];
            float bbx = sBias[64 + lc], bby = sBias[64 + lc + 1];
            if (v0) {
                float2 v;
                v.x = wa0 * (acc[0][mt][nt][0] + bax) + wb0 * (acc[1][mt][nt][0] + bbx);
                v.y = wa0 * (acc[0][mt][nt][1] + bay) + wb0 * (acc[1][mt][nt][1] + bby);
                *(float2*)(o0 + lc) = v;
            }
            if (v1) {
                float2 v;
                v.x = wa1 * (acc[0][mt][nt][2] + bax) + wb1 * (acc[1][mt][nt][2] + bbx);
                v.y = wa1 * (acc[0][mt][nt][3] + bay) + wb1 * (acc[1][mt][nt][3] + bby);
                *(float2*)(o1 + lc) = v;
            }
        }
    }
}

// ---------------- launch ----------------
extern "C" void kernel_launch(void* const* d_in, const int* in_sizes, int n_in,
                              void* d_out, int out_size)
{
    const float* x  = (const float*)d_in[0];
    const float* rw = (const float*)d_in[1];
    const float* rb = (const float*)d_in[2];
    const float* ew = (const float*)d_in[3];
    const float* eb = (const float*)d_in[4];
    float* out = (float*)d_out;
    (void)in_sizes; (void)n_in; (void)out_size;

    cudaFuncSetAttribute(moe_pair, cudaFuncAttributeMaxDynamicSharedMemorySize, SMEM_BYTES);

    prep_kernel<<<RBLK + WBLK, 256>>>(x, rw, rb, ew);
    moe_pair<<<dim3(HDIM / 64, MAXT2), 256, SMEM_BYTES>>>(eb, out);
}

// round 13
// speedup vs baseline: 1.0057x; 1.0057x over previous
#include <cuda_runtime.h>
#include <cuda_fp16.h>
#include <cstdint>

#define NTOK 32768
#define HDIM 768
#define NEXP 8
#define NPAIR 28
#define TM 128
#define MAXT2 (NTOK / TM + NPAIR)    // 284

// GEMM tiles (proven mainloop config)
#define CTM 128
#define CTK 32
#define KT  (HDIM / CTK)              // 24 stages
#define NSTG 4
#define ROWB 80
#define TILEB (128 * ROWB)            // 10240
#define STAGEB (2 * TILEB)
#define SMEM_BYTES (NSTG * STAGEB)    // 81920 -> 2 CTAs/SM

#define RBLK (NTOK / 8)               // 4096 router blocks
#define WBLK (NEXP * HDIM * HDIM / 1024)  // 4608 convert blocks

typedef unsigned long long u64;

// ---------------- scratch ----------------
__device__ int   g_cnt [NPAIR];       // zero at load; last prep block re-zeros per replay
__device__ int   g_mend[NPAIR];
__device__ int   g_ts  [NPAIR + 1];
__device__ int   g_done;
__device__ int   g_tok [NPAIR][NTOK];
__device__ float g_pwa [NPAIR][NTOK];
__device__ float g_pwb [NPAIR][NTOK];

__device__ __half g_xh[NTOK * HDIM];
__device__ __half g_wh[NEXP * HDIM * HDIM];

// ---------------- helpers ----------------
__device__ __forceinline__ void cpa16(uint32_t s, const void* g) {
    asm volatile("cp.async.cg.shared.global [%0], [%1], 16;" :: "r"(s), "l"(g));
}
__device__ __forceinline__ void cp_commit() { asm volatile("cp.async.commit_group;"); }
template <int N> __device__ __forceinline__ void cp_wait() {
    asm volatile("cp.async.wait_group %0;" :: "n"(N));
}
__device__ __forceinline__ void mma16816_f32(float* c, const uint32_t* a, const uint32_t* b) {
    asm volatile(
        "mma.sync.aligned.m16n8k16.row.col.f32.f16.f16.f32 "
        "{%0,%1,%2,%3}, {%4,%5,%6,%7}, {%8,%9}, {%0,%1,%2,%3};"
        : "+f"(c[0]), "+f"(c[1]), "+f"(c[2]), "+f"(c[3])
        : "r"(a[0]), "r"(a[1]), "r"(a[2]), "r"(a[3]), "r"(b[0]), "r"(b[1]));
}
__device__ __forceinline__ void ldsm4(uint32_t* r, uint32_t addr) {
    asm volatile("ldmatrix.sync.aligned.m8n8.x4.shared.b16 {%0,%1,%2,%3}, [%4];"
        : "=r"(r[0]), "=r"(r[1]), "=r"(r[2]), "=r"(r[3]) : "r"(addr));
}
__device__ __forceinline__ int pair_id(int a, int b) {   // a < b
    return a * (2 * NEXP - 1 - a) / 2 + (b - a - 1);
}

// ---------------- kernel 1: fused prep — router + weight convert + inline scan ----------------
__global__ __launch_bounds__(256) void prep_kernel(
    const float* __restrict__ x, const float* __restrict__ rw,
    const float* __restrict__ rb, const float* __restrict__ w)
{
    if (blockIdx.x >= RBLK) {
        // ---- weight convert path ----
        int i = (blockIdx.x - RBLK) * 256 + threadIdx.x;   // one float4 per thread
        float4 v = ((const float4*)w)[i];
        ((__half2*)g_wh)[2 * i]     = __floats2half2_rn(v.x, v.y);
        ((__half2*)g_wh)[2 * i + 1] = __floats2half2_rn(v.z, v.w);
    } else {
        // ---- router path (fused x hi conversion + direct bucket write) ----
        __shared__ float s_rw[NEXP * HDIM];
        for (int i = threadIdx.x; i < NEXP * HDIM; i += 256) s_rw[i] = rw[i];
        __syncthreads();

        int warp = threadIdx.x >> 5, lane = threadIdx.x & 31;
        int tok = (blockIdx.x << 3) + warp;
        const float4* xr = (const float4*)(x + (size_t)tok * HDIM);
        __half2* xh = (__half2*)(g_xh + (size_t)tok * HDIM);

        float acc[NEXP];
#pragma unroll
        for (int e = 0; e < NEXP; e++) acc[e] = 0.f;
#pragma unroll
        for (int i = 0; i < HDIM / 128; i++) {
            int idx = i * 32 + lane;
            float4 v = xr[idx];
            xh[2 * idx]     = __floats2half2_rn(v.x, v.y);
            xh[2 * idx + 1] = __floats2half2_rn(v.z, v.w);
#pragma unroll
            for (int e = 0; e < NEXP; e++) {
                float4 w4 = ((const float4*)(s_rw + e * HDIM))[idx];
                acc[e] = fmaf(v.x, w4.x, fmaf(v.y, w4.y, fmaf(v.z, w4.z, fmaf(v.w, w4.w, acc[e]))));
            }
        }
#pragma unroll
        for (int e = 0; e < NEXP; e++)
#pragma unroll
            for (int o = 16; o > 0; o >>= 1)
                acc[e] += __shfl_xor_sync(0xffffffffu, acc[e], o);

        if (lane == 0) {
            float s[NEXP];
#pragma unroll
            for (int e = 0; e < NEXP; e++) s[e] = acc[e] + rb[e];
            float m = s[0];
#pragma unroll
            for (int e = 1; e < NEXP; e++) m = fmaxf(m, s[e]);
            float p[NEXP]; float Z = 0.f;
#pragma unroll
            for (int e = 0; e < NEXP; e++) { p[e] = expf(s[e] - m); Z += p[e]; }
            int e0 = 0;
#pragma unroll
            for (int e = 1; e < NEXP; e++) if (p[e] > p[e0]) e0 = e;
            int e1 = (e0 == 0) ? 1 : 0;
#pragma unroll
            for (int e = 0; e < NEXP; e++) if (e != e0 && p[e] > p[e1]) e1 = e;
            float p0 = p[e0] / Z, p1 = p[e1] / Z;
            float inv = 1.f / (p0 + p1 + 1e-9f);
            int a = min(e0, e1), b = max(e0, e1);
            float wa = (e0 < e1) ? p0 * inv : p1 * inv;
            float wb = (e0 < e1) ? p1 * inv : p0 * inv;
            int pid = pair_id(a, b);
            int pos = atomicAdd(&g_cnt[pid], 1);
            g_tok[pid][pos] = tok;
            g_pwa[pid][pos] = wa;
            g_pwb[pid][pos] = wb;
        }
    }

    // ---- last-block-done: inline scan (replaces scan_kernel) ----
    __syncthreads();
    __threadfence();
    if (threadIdx.x == 0) {
        int ticket = atomicAdd(&g_done, 1);
        if (ticket == (int)gridDim.x - 1) {
            g_done = 0;                      // reset for next graph replay
            int t = 0;
            for (int p = 0; p < NPAIR; p++) {
                g_ts[p] = t;
                int c = g_cnt[p];
                g_mend[p] = c;
                g_cnt[p] = 0;                // reset for next graph replay
                t += (c + TM - 1) >> 7;
            }
            g_ts[NPAIR] = t;
            __threadfence();
        }
    }
}

// ---------------- kernel 2: pair GEMM — pair-tile on x (r11 order), N-tile on y ----------------
__global__ __launch_bounds__(256, 2)
void moe_pair(const float* __restrict__ eb, float* __restrict__ out)
{
    extern __shared__ __align__(128) char smem[];
    const uint32_t sb = (uint32_t)__cvta_generic_to_shared(smem);

    __shared__ int   sMeta[3];
    __shared__ int   sTok[CTM];
    __shared__ float sWa[CTM];
    __shared__ float sWb[CTM];
    __shared__ float sBias[128];

    int tid = threadIdx.x;
    int wid = tid >> 5, lane = tid & 31;

    if (tid == 0) {
        int bx = blockIdx.x;                 // pair-tile index (r11 order)
        if (bx >= g_ts[NPAIR]) sMeta[0] = -1;
        else {
            int p = 0;
            while (g_ts[p + 1] <= bx) p++;
            sMeta[0] = p;
            sMeta[1] = (bx - g_ts[p]) << 7;
            sMeta[2] = g_mend[p];
        }
    }
    __syncthreads();
    int p = sMeta[0];
    if (p < 0) return;
    int m0 = sMeta[1], mEnd = sMeta[2];
    // decode pair -> (ea, eb_)
    int ea = 0, rem = p, span = NEXP - 1;
    while (rem >= span) { rem -= span; ea++; span--; }
    int eb_ = ea + 1 + rem;
    int nBase = blockIdx.y << 6;             // N-tile * 64

    if (tid < CTM) {
        int pp = m0 + tid;
        int pc = pp < mEnd ? pp : mEnd - 1;
        sTok[tid] = g_tok[p][pc];
        sWa[tid]  = g_pwa[p][pc];
        sWb[tid]  = g_pwb[p][pc];
    }
    if (tid < 128) {
        int ex = (tid < 64) ? ea : eb_;
        sBias[tid] = __ldg(eb + ex * HDIM + nBase + (tid & 63));
    }
    __syncthreads();

    // ---- stage loader ----
    int lrow = tid >> 1;
    int lc0  = (tid & 1) * 2;
    size_t gAr = (size_t)sTok[lrow] * HDIM;
    int bexp = (lrow < 64) ? ea : eb_;
    size_t gBr = ((size_t)bexp * HDIM + nBase + (lrow & 63)) * HDIM;

    auto load_stage = [&](int kt, int buf) {
        uint32_t sbase = sb + (uint32_t)buf * STAGEB;
        int kc = kt * CTK;
#pragma unroll
        for (int t = 0; t < 2; t++) {
            int c = lc0 + t;
            uint32_t so = (uint32_t)(lrow * ROWB + c * 16);
            cpa16(sbase + 0 * TILEB + so, g_xh + gAr + kc + c * 8);
            cpa16(sbase + 1 * TILEB + so, g_wh + gBr + kc + c * 8);
        }
    };

    load_stage(0, 0); cp_commit();
    load_stage(1, 1); cp_commit();
    load_stage(2, 2); cp_commit();

    int warp_m = wid >> 1, warp_n = wid & 1;
    int r = lane >> 2, q = lane & 3;

    uint32_t aOff = (uint32_t)((warp_m * 32 + (lane & 15)) * ROWB + ((lane >> 4) << 4));
    uint32_t bLane = (uint32_t)((((lane >> 4) << 3) + (lane & 7)) * ROWB
                                + (((lane >> 3) & 1) << 4));

    float acc[2][2][4][4];
#pragma unroll
    for (int x = 0; x < 2; x++)
#pragma unroll
        for (int mt = 0; mt < 2; mt++)
#pragma unroll
            for (int nt = 0; nt < 4; nt++)
#pragma unroll
                for (int i = 0; i < 4; i++) acc[x][mt][nt][i] = 0.f;

    for (int kt = 0; kt < KT; kt++) {
        int buf = kt & 3;
        if (kt <= KT - 3) cp_wait<2>();
        else if (kt == KT - 2) cp_wait<1>();
        else cp_wait<0>();
        __syncthreads();
        if (kt + 3 < KT) { load_stage(kt + 3, (kt + 3) & 3); cp_commit(); }

        uint32_t tb = sb + (uint32_t)buf * STAGEB;

#pragma unroll
        for (int k16 = 0; k16 < 2; k16++) {
            uint32_t kb = (uint32_t)(k16 * 32);
            uint32_t ah[2][4], bf[2][4][2];
#pragma unroll
            for (int mt = 0; mt < 2; mt++)
                ldsm4(ah[mt], tb + aOff + (uint32_t)(mt * 16 * ROWB) + kb);
#pragma unroll
            for (int x = 0; x < 2; x++)
#pragma unroll
                for (int ntp = 0; ntp < 2; ntp++) {
                    uint32_t regs[4];
                    uint32_t grpRow = (uint32_t)((x * 64 + warp_n * 32 + ntp * 16) * ROWB);
                    ldsm4(regs, tb + TILEB + bLane + grpRow + kb);
                    bf[x][2 * ntp][0] = regs[0]; bf[x][2 * ntp][1] = regs[1];
                    bf[x][2 * ntp + 1][0] = regs[2]; bf[x][2 * ntp + 1][1] = regs[3];
                }
#pragma unroll
            for (int x = 0; x < 2; x++)
#pragma unroll
                for (int mt = 0; mt < 2; mt++)
#pragma unroll
                    for (int nt = 0; nt < 4; nt++)
                        mma16816_f32(acc[x][mt][nt], ah[mt], bf[x][nt]);
        }
    }

    // ---- epilogue: out = wa*(ya+ba) + wb*(yb+bb) ----
#pragma unroll
    for (int mt = 0; mt < 2; mt++) {
        int lr0 = warp_m * 32 + mt * 16 + r;
        int lr1 = lr0 + 8;
        bool v0 = (m0 + lr0) < mEnd;
        bool v1 = (m0 + lr1) < mEnd;
        float wa0 = sWa[lr0], wb0 = sWb[lr0];
        float wa1 = sWa[lr1], wb1 = sWb[lr1];
        float* o0 = out + (size_t)sTok[lr0] * HDIM + nBase;
        float* o1 = out + (size_t)sTok[lr1] * HDIM + nBase;
#pragma unroll
        for (int nt = 0; nt < 4; nt++) {
            int lc = warp_n * 32 + nt * 8 + 2 * q;
            float bax = sBias[lc], bay = sBias[lc + 1];
            float bbx = sBias[64 + lc], bby = sBias[64 + lc + 1];
            if (v0) {
                float2 v;
                v.x = wa0 * (acc[0][mt][nt][0] + bax) + wb0 * (acc[1][mt][nt][0] + bbx);
                v.y = wa0 * (acc[0][mt][nt][1] + bay) + wb0 * (acc[1][mt][nt][1] + bby);
                *(float2*)(o0 + lc) = v;
            }
            if (v1) {
                float2 v;
                v.x = wa1 * (acc[0][mt][nt][2] + bax) + wb1 * (acc[1][mt][nt][2] + bbx);
                v.y = wa1 * (acc[0][mt][nt][3] + bay) + wb1 * (acc[1][mt][nt][3] + bby);
                *(float2*)(o1 + lc) = v;
            }
        }
    }
}

// ---------------- launch ----------------
extern "C" void kernel_launch(void* const* d_in, const int* in_sizes, int n_in,
                              void* d_out, int out_size)
{
    const float* x  = (const float*)d_in[0];
    const float* rw = (const float*)d_in[1];
    const float* rb = (const float*)d_in[2];
    const float* ew = (const float*)d_in[3];
    const float* eb = (const float*)d_in[4];
    float* out = (float*)d_out;
    (void)in_sizes; (void)n_in; (void)out_size;

    cudaFuncSetAttribute(moe_pair, cudaFuncAttributeMaxDynamicSharedMemorySize, SMEM_BYTES);

    prep_kernel<<<RBLK + WBLK, 256>>>(x, rw, rb, ew);
    moe_pair<<<dim3(MAXT2, HDIM / 64), 256, SMEM_BYTES>>>(eb, out);
}

// round 14
// speedup vs baseline: 1.0411x; 1.0352x over previous
#include <cuda_runtime.h>
#include <cuda_fp16.h>
#include <cstdint>

#define NTOK 32768
#define HDIM 768
#define NEXP 8
#define NPAIR 28
#define TM 128
#define NT (HDIM / 64)               // 12 N-tiles

// GEMM tiles (proven mainloop config)
#define CTM 128
#define CTK 32
#define KT  (HDIM / CTK)              // 24 stages
#define NSTG 4
#define ROWB 80
#define TILEB (128 * ROWB)            // 10240
#define STAGEB (2 * TILEB)
#define SMEM_BYTES (NSTG * STAGEB)    // 81920 -> 2 CTAs/SM

#define RBLK (NTOK / 8)               // 4096 router blocks
#define WBLK (NEXP * HDIM * HDIM / 1024)  // 4608 convert blocks
#define NPERS 296                     // persistent CTAs: 148 SMs x 2

typedef unsigned long long u64;

// ---------------- scratch ----------------
__device__ int   g_cnt [NPAIR];       // zero at load; scan re-zeros per replay
__device__ int   g_mend[NPAIR];
__device__ int   g_ts  [NPAIR + 1];
__device__ int   g_work;              // persistent work cursor (scan resets)
__device__ int   g_total;
__device__ int   g_tok [NPAIR][NTOK];
__device__ float g_pwa [NPAIR][NTOK];
__device__ float g_pwb [NPAIR][NTOK];

__device__ __half g_xh[NTOK * HDIM];
__device__ __half g_wh[NEXP * HDIM * HDIM];

// ---------------- helpers ----------------
__device__ __forceinline__ void cpa16(uint32_t s, const void* g) {
    asm volatile("cp.async.cg.shared.global [%0], [%1], 16;" :: "r"(s), "l"(g));
}
__device__ __forceinline__ void cp_commit() { asm volatile("cp.async.commit_group;"); }
template <int N> __device__ __forceinline__ void cp_wait() {
    asm volatile("cp.async.wait_group %0;" :: "n"(N));
}
__device__ __forceinline__ void mma16816_f32(float* c, const uint32_t* a, const uint32_t* b) {
    asm volatile(
        "mma.sync.aligned.m16n8k16.row.col.f32.f16.f16.f32 "
        "{%0,%1,%2,%3}, {%4,%5,%6,%7}, {%8,%9}, {%0,%1,%2,%3};"
        : "+f"(c[0]), "+f"(c[1]), "+f"(c[2]), "+f"(c[3])
        : "r"(a[0]), "r"(a[1]), "r"(a[2]), "r"(a[3]), "r"(b[0]), "r"(b[1]));
}
__device__ __forceinline__ void ldsm4(uint32_t* r, uint32_t addr) {
    asm volatile("ldmatrix.sync.aligned.m8n8.x4.shared.b16 {%0,%1,%2,%3}, [%4];"
        : "=r"(r[0]), "=r"(r[1]), "=r"(r[2]), "=r"(r[3]) : "r"(addr));
}
__device__ __forceinline__ int pair_id(int a, int b) {   // a < b
    return a * (2 * NEXP - 1 - a) / 2 + (b - a - 1);
}

// ---------------- kernel 1: fused prep — router + weight convert ----------------
__global__ __launch_bounds__(256) void prep_kernel(
    const float* __restrict__ x, const float* __restrict__ rw,
    const float* __restrict__ rb, const float* __restrict__ w)
{
    if (blockIdx.x >= RBLK) {
        int i = (blockIdx.x - RBLK) * 256 + threadIdx.x;
        float4 v = ((const float4*)w)[i];
        ((__half2*)g_wh)[2 * i]     = __floats2half2_rn(v.x, v.y);
        ((__half2*)g_wh)[2 * i + 1] = __floats2half2_rn(v.z, v.w);
        return;
    }

    __shared__ float s_rw[NEXP * HDIM];
    for (int i = threadIdx.x; i < NEXP * HDIM; i += 256) s_rw[i] = rw[i];
    __syncthreads();

    int warp = threadIdx.x >> 5, lane = threadIdx.x & 31;
    int tok = (blockIdx.x << 3) + warp;
    const float4* xr = (const float4*)(x + (size_t)tok * HDIM);
    __half2* xh = (__half2*)(g_xh + (size_t)tok * HDIM);

    float acc[NEXP];
#pragma unroll
    for (int e = 0; e < NEXP; e++) acc[e] = 0.f;
#pragma unroll
    for (int i = 0; i < HDIM / 128; i++) {
        int idx = i * 32 + lane;
        float4 v = xr[idx];
        xh[2 * idx]     = __floats2half2_rn(v.x, v.y);
        xh[2 * idx + 1] = __floats2half2_rn(v.z, v.w);
#pragma unroll
        for (int e = 0; e < NEXP; e++) {
            float4 w4 = ((const float4*)(s_rw + e * HDIM))[idx];
            acc[e] = fmaf(v.x, w4.x, fmaf(v.y, w4.y, fmaf(v.z, w4.z, fmaf(v.w, w4.w, acc[e]))));
        }
    }
#pragma unroll
    for (int e = 0; e < NEXP; e++)
#pragma unroll
        for (int o = 16; o > 0; o >>= 1)
            acc[e] += __shfl_xor_sync(0xffffffffu, acc[e], o);

    if (lane == 0) {
        float s[NEXP];
#pragma unroll
        for (int e = 0; e < NEXP; e++) s[e] = acc[e] + rb[e];
        float m = s[0];
#pragma unroll
        for (int e = 1; e < NEXP; e++) m = fmaxf(m, s[e]);
        float p[NEXP]; float Z = 0.f;
#pragma unroll
        for (int e = 0; e < NEXP; e++) { p[e] = expf(s[e] - m); Z += p[e]; }
        int e0 = 0;
#pragma unroll
        for (int e = 1; e < NEXP; e++) if (p[e] > p[e0]) e0 = e;
        int e1 = (e0 == 0) ? 1 : 0;
#pragma unroll
        for (int e = 0; e < NEXP; e++) if (e != e0 && p[e] > p[e1]) e1 = e;
        float p0 = p[e0] / Z, p1 = p[e1] / Z;
        float inv = 1.f / (p0 + p1 + 1e-9f);
        int a = min(e0, e1), b = max(e0, e1);
        float wa = (e0 < e1) ? p0 * inv : p1 * inv;
        float wb = (e0 < e1) ? p1 * inv : p0 * inv;
        int pid = pair_id(a, b);
        int pos = atomicAdd(&g_cnt[pid], 1);
        g_tok[pid][pos] = tok;
        g_pwa[pid][pos] = wa;
        g_pwb[pid][pos] = wb;
    }
}

// ---------------- kernel 2: scan (tile prefix + work-queue init + counter reset) ----------------
__global__ void scan_kernel() {
    if (threadIdx.x == 0 && blockIdx.x == 0) {
        int t = 0;
        for (int p = 0; p < NPAIR; p++) {
            g_ts[p] = t;
            int c = g_cnt[p];
            g_mend[p] = c;
            g_cnt[p] = 0;                // reset for next graph replay
            t += (c + TM - 1) >> 7;
        }
        g_ts[NPAIR] = t;
        g_work = 0;                      // reset work cursor
        g_total = t * NT;
    }
}

// ---------------- kernel 3: persistent pair GEMM with atomic work queue ----------------
__global__ __launch_bounds__(256, 2)
void moe_pair(const float* __restrict__ eb, float* __restrict__ out)
{
    extern __shared__ __align__(128) char smem[];
    const uint32_t sb = (uint32_t)__cvta_generic_to_shared(smem);

    __shared__ int   sMeta[4];          // [item, p, m0, mEnd]
    __shared__ int   sTok[CTM];
    __shared__ float sWa[CTM];
    __shared__ float sWb[CTM];
    __shared__ float sBias[128];

    int tid = threadIdx.x;
    int wid = tid >> 5, lane = tid & 31;
    int warp_m = wid >> 1, warp_n = wid & 1;
    int r = lane >> 2, q = lane & 3;

    uint32_t aOff = (uint32_t)((warp_m * 32 + (lane & 15)) * ROWB + ((lane >> 4) << 4));
    uint32_t bLane = (uint32_t)((((lane >> 4) << 3) + (lane & 7)) * ROWB
                                + (((lane >> 3) & 1) << 4));
    int lrow = tid >> 1;
    int lc0  = (tid & 1) * 2;

    while (true) {
        __syncthreads();                // protect smem reuse across iterations
        if (tid == 0) {
            int item = atomicAdd(&g_work, 1);
            sMeta[0] = (item < g_total) ? item : -1;
            if (item < g_total) {
                int T = g_ts[NPAIR];
                int tile = item % T;
                int p = 0;
                while (g_ts[p + 1] <= tile) p++;
                sMeta[1] = p;
                sMeta[2] = (tile - g_ts[p]) << 7;
                sMeta[3] = (item / T) << 6;   // nBase
            }
        }
        __syncthreads();
        if (sMeta[0] < 0) break;
        int p = sMeta[1];
        int m0 = sMeta[2];
        int nBase = sMeta[3];
        int mEnd = g_mend[p];
        // decode pair -> (ea, eb_)
        int ea = 0, rem = p, span = NEXP - 1;
        while (rem >= span) { rem -= span; ea++; span--; }
        int eb_ = ea + 1 + rem;

        if (tid < CTM) {
            int pp = m0 + tid;
            int pc = pp < mEnd ? pp : mEnd - 1;
            sTok[tid] = g_tok[p][pc];
            sWa[tid]  = g_pwa[p][pc];
            sWb[tid]  = g_pwb[p][pc];
        }
        if (tid < 128) {
            int ex = (tid < 64) ? ea : eb_;
            sBias[tid] = __ldg(eb + ex * HDIM + nBase + (tid & 63));
        }
        __syncthreads();

        size_t gAr = (size_t)sTok[lrow] * HDIM;
        int bexp = (lrow < 64) ? ea : eb_;
        size_t gBr = ((size_t)bexp * HDIM + nBase + (lrow & 63)) * HDIM;

        auto load_stage = [&](int kt, int buf) {
            uint32_t sbase = sb + (uint32_t)buf * STAGEB;
            int kc = kt * CTK;
#pragma unroll
            for (int t = 0; t < 2; t++) {
                int c = lc0 + t;
                uint32_t so = (uint32_t)(lrow * ROWB + c * 16);
                cpa16(sbase + 0 * TILEB + so, g_xh + gAr + kc + c * 8);
                cpa16(sbase + 1 * TILEB + so, g_wh + gBr + kc + c * 8);
            }
        };

        load_stage(0, 0); cp_commit();
        load_stage(1, 1); cp_commit();
        load_stage(2, 2); cp_commit();

        float acc[2][2][4][4];
#pragma unroll
        for (int x = 0; x < 2; x++)
#pragma unroll
            for (int mt = 0; mt < 2; mt++)
#pragma unroll
                for (int nt = 0; nt < 4; nt++)
#pragma unroll
                    for (int i = 0; i < 4; i++) acc[x][mt][nt][i] = 0.f;

        for (int kt = 0; kt < KT; kt++) {
            int buf = kt & 3;
            if (kt <= KT - 3) cp_wait<2>();
            else if (kt == KT - 2) cp_wait<1>();
            else cp_wait<0>();
            __syncthreads();
            if (kt + 3 < KT) { load_stage(kt + 3, (kt + 3) & 3); cp_commit(); }

            uint32_t tb = sb + (uint32_t)buf * STAGEB;

#pragma unroll
            for (int k16 = 0; k16 < 2; k16++) {
                uint32_t kb = (uint32_t)(k16 * 32);
                uint32_t ah[2][4], bf[2][4][2];
#pragma unroll
                for (int mt = 0; mt < 2; mt++)
                    ldsm4(ah[mt], tb + aOff + (uint32_t)(mt * 16 * ROWB) + kb);
#pragma unroll
                for (int x = 0; x < 2; x++)
#pragma unroll
                    for (int ntp = 0; ntp < 2; ntp++) {
                        uint32_t regs[4];
                        uint32_t grpRow = (uint32_t)((x * 64 + warp_n * 32 + ntp * 16) * ROWB);
                        ldsm4(regs, tb + TILEB + bLane + grpRow + kb);
                        bf[x][2 * ntp][0] = regs[0]; bf[x][2 * ntp][1] = regs[1];
                        bf[x][2 * ntp + 1][0] = regs[2]; bf[x][2 * ntp + 1][1] = regs[3];
                    }
#pragma unroll
                for (int x = 0; x < 2; x++)
#pragma unroll
                    for (int mt = 0; mt < 2; mt++)
#pragma unroll
                        for (int nt = 0; nt < 4; nt++)
                            mma16816_f32(acc[x][mt][nt], ah[mt], bf[x][nt]);
            }
        }

        // ---- epilogue: out = wa*(ya+ba) + wb*(yb+bb) ----
#pragma unroll
        for (int mt = 0; mt < 2; mt++) {
            int lr0 = warp_m * 32 + mt * 16 + r;
            int lr1 = lr0 + 8;
            bool v0 = (m0 + lr0) < mEnd;
            bool v1 = (m0 + lr1) < mEnd;
            float wa0 = sWa[lr0], wb0 = sWb[lr0];
            float wa1 = sWa[lr1], wb1 = sWb[lr1];
            float* o0 = out + (size_t)sTok[lr0] * HDIM + nBase;
            float* o1 = out + (size_t)sTok[lr1] * HDIM + nBase;
#pragma unroll
            for (int nt = 0; nt < 4; nt++) {
                int lc = warp_n * 32 + nt * 8 + 2 * q;
                float bax = sBias[lc], bay = sBias[lc + 1];
                float bbx = sBias[64 + lc], bby = sBias[64 + lc + 1];
                if (v0) {
                    float2 v;
                    v.x = wa0 * (acc[0][mt][nt][0] + bax) + wb0 * (acc[1][mt][nt][0] + bbx);
                    v.y = wa0 * (acc[0][mt][nt][1] + bay) + wb0 * (acc[1][mt][nt][1] + bby);
                    *(float2*)(o0 + lc) = v;
                }
                if (v1) {
                    float2 v;
                    v.x = wa1 * (acc[0][mt][nt][2] + bax) + wb1 * (acc[1][mt][nt][2] + bbx);
                    v.y = wa1 * (acc[0][mt][nt][3] + bay) + wb1 * (acc[1][mt][nt][3] + bby);
                    *(float2*)(o1 + lc) = v;
                }
            }
        }
    }
}

// ---------------- launch ----------------
extern "C" void kernel_launch(void* const* d_in, const int* in_sizes, int n_in,
                              void* d_out, int out_size)
{
    const float* x  = (const float*)d_in[0];
    const float* rw = (const float*)d_in[1];
    const float* rb = (const float*)d_in[2];
    const float* ew = (const float*)d_in[3];
    const float* eb = (const float*)d_in[4];
    float* out = (float*)d_out;
    (void)in_sizes; (void)n_in; (void)out_size;

    cudaFuncSetAttribute(moe_pair, cudaFuncAttributeMaxDynamicSharedMemorySize, SMEM_BYTES);

    prep_kernel<<<RBLK + WBLK, 256>>>(x, rw, rb, ew);
    scan_kernel<<<1, 32>>>();
    moe_pair<<<NPERS, 256, SMEM_BYTES>>>(eb, out);
}